// round 1
// baseline (speedup 1.0000x reference)
#include <cuda_runtime.h>
#include <math.h>

// Problem constants
#define T_  2048
#define B_  2
#define S_  2048
#define E_  1024
#define H_  16
#define HD_ 64
#define R_  16
#define M_  (T_ * B_)          // 4096 rows for projections
#define BH_ (B_ * H_)          // 32 attention "batches"
#define SCALING 1.0f           // ALPHA / R = 16/16
#define OUT1_ELEMS ((size_t)T_ * B_ * E_)            // 4,194,304
#define OUT2_ELEMS ((size_t)B_ * T_ * S_)            // 8,388,608

// ---------------------------------------------------------------------------
// Static device scratch (no allocations allowed)
// ---------------------------------------------------------------------------
__device__ float g_Q[M_ * E_];                        // 16 MB
__device__ float g_K[M_ * E_];                        // 16 MB
__device__ float g_V[M_ * E_];                        // 16 MB
__device__ float g_O[M_ * E_];                        // 16 MB (attention out, (t*B+b, E))
__device__ float g_P[(size_t)BH_ * T_ * S_];          // 512 MB scores/probs
__device__ float g_Xa[4 * M_ * R_];                   // LoRA-A activations (q,k,v,o)

// ---------------------------------------------------------------------------
// Kernel 1: LoRA-A  Xa[m,r] = sum_e X[m,e] * la[r,e]
// one block (128 thr) per row m
// ---------------------------------------------------------------------------
__global__ void lora_a_kernel(const float* __restrict__ X,
                              const float* __restrict__ la,
                              float* __restrict__ Xa) {
    int m = blockIdx.x;
    int t = threadIdx.x;          // 128
    int r  = t & 15;
    int eo = t >> 4;              // 0..7
    const float* x   = X  + (size_t)m * E_;
    const float* lar = la + (size_t)r * E_;
    float acc = 0.f;
    #pragma unroll 8
    for (int e = eo; e < E_; e += 8) acc += x[e] * lar[e];
    __shared__ float sm[16][8];
    sm[r][eo] = acc;
    __syncthreads();
    if (t < 16) {
        float s = 0.f;
        #pragma unroll
        for (int i = 0; i < 8; i++) s += sm[t][i];
        Xa[(size_t)m * R_ + t] = s;
    }
}

// ---------------------------------------------------------------------------
// Kernel 2: C[m,n] = sum_k A[m,k]*W[n,k] + bias[n] + SCALING * sum_r Xa[m,r]*lb[n,r]
// 128x128x8 tile, 256 threads, 8x8 per thread.  M=4096, N=1024, K=1024.
// ---------------------------------------------------------------------------
__global__ __launch_bounds__(256, 2)
void gemm_lora_kernel(const float* __restrict__ A, const float* __restrict__ W,
                      const float* __restrict__ bias, const float* __restrict__ Xa,
                      const float* __restrict__ lb, float* __restrict__ C) {
    const int N = E_, K = E_;
    __shared__ float As[8][128];
    __shared__ float Ws[8][128];

    int tid = threadIdx.x;
    int m0 = blockIdx.y * 128;
    int n0 = blockIdx.x * 128;

    int lr = tid >> 1;              // 0..127
    int lq = (tid & 1) * 4;         // 0 or 4
    int tm = (tid >> 4) * 8;        // 0..120
    int tn = (tid & 15) * 8;        // 0..120

    float acc[8][8];
    #pragma unroll
    for (int i = 0; i < 8; i++)
        #pragma unroll
        for (int j = 0; j < 8; j++) acc[i][j] = 0.f;

    const float* Aptr = A + (size_t)(m0 + lr) * K + lq;
    const float* Wptr = W + (size_t)(n0 + lr) * K + lq;

    for (int k0 = 0; k0 < K; k0 += 8) {
        float4 av = *(const float4*)(Aptr + k0);
        float4 wv = *(const float4*)(Wptr + k0);
        As[lq + 0][lr] = av.x; As[lq + 1][lr] = av.y;
        As[lq + 2][lr] = av.z; As[lq + 3][lr] = av.w;
        Ws[lq + 0][lr] = wv.x; Ws[lq + 1][lr] = wv.y;
        Ws[lq + 2][lr] = wv.z; Ws[lq + 3][lr] = wv.w;
        __syncthreads();
        #pragma unroll
        for (int k = 0; k < 8; k++) {
            float4 a0 = *(const float4*)&As[k][tm];
            float4 a1 = *(const float4*)&As[k][tm + 4];
            float4 b0 = *(const float4*)&Ws[k][tn];
            float4 b1 = *(const float4*)&Ws[k][tn + 4];
            float ar[8] = {a0.x, a0.y, a0.z, a0.w, a1.x, a1.y, a1.z, a1.w};
            float br[8] = {b0.x, b0.y, b0.z, b0.w, b1.x, b1.y, b1.z, b1.w};
            #pragma unroll
            for (int i = 0; i < 8; i++)
                #pragma unroll
                for (int j = 0; j < 8; j++)
                    acc[i][j] += ar[i] * br[j];
        }
        __syncthreads();
    }

    // epilogue: bias + rank-16 LoRA-B
    #pragma unroll
    for (int i = 0; i < 8; i++) {
        int m = m0 + tm + i;
        float xa[R_];
        #pragma unroll
        for (int r = 0; r < R_; r++) xa[r] = Xa[(size_t)m * R_ + r];
        #pragma unroll
        for (int j = 0; j < 8; j++) {
            int n = n0 + tn + j;
            float l = 0.f;
            const float* lbn = lb + (size_t)n * R_;
            #pragma unroll
            for (int r = 0; r < R_; r++) l += xa[r] * lbn[r];
            C[(size_t)m * N + n] = acc[i][j] + bias[n] + SCALING * l;
        }
    }
}

// ---------------------------------------------------------------------------
// Kernel 3: scores  P[bh, t, s] = (1/8) * sum_d Q[t,b,h*64+d] * K[s,b,h*64+d]
// 64x64 tile per block, 256 threads, 4x4 per thread, K=64 fully staged.
// ---------------------------------------------------------------------------
__global__ __launch_bounds__(256)
void scores_kernel(const float* __restrict__ Q, const float* __restrict__ Kp,
                   float* __restrict__ P) {
    int bh = blockIdx.z;
    int b = bh >> 4, h = bh & 15;
    int t0 = blockIdx.y * 64;
    int s0 = blockIdx.x * 64;

    __shared__ float Qs[64][65];   // [d][t]
    __shared__ float Ks[64][65];   // [d][s]

    int tid = threadIdx.x;
    // load 64 rows x 64 d each (4 float4 / thread, transposed store)
    #pragma unroll
    for (int i = 0; i < 4; i++) {
        int row  = (tid >> 4) + i * 16;
        int dcol = (tid & 15) * 4;
        size_t qa = ((size_t)(t0 + row) * B_ + b) * E_ + h * HD_ + dcol;
        size_t ka = ((size_t)(s0 + row) * B_ + b) * E_ + h * HD_ + dcol;
        float4 qv = *(const float4*)(Q + qa);
        float4 kv = *(const float4*)(Kp + ka);
        Qs[dcol + 0][row] = qv.x; Qs[dcol + 1][row] = qv.y;
        Qs[dcol + 2][row] = qv.z; Qs[dcol + 3][row] = qv.w;
        Ks[dcol + 0][row] = kv.x; Ks[dcol + 1][row] = kv.y;
        Ks[dcol + 2][row] = kv.z; Ks[dcol + 3][row] = kv.w;
    }
    __syncthreads();

    int tm = (tid >> 4) * 4;
    int tn = (tid & 15) * 4;
    float acc[4][4];
    #pragma unroll
    for (int i = 0; i < 4; i++)
        #pragma unroll
        for (int j = 0; j < 4; j++) acc[i][j] = 0.f;

    #pragma unroll 8
    for (int k = 0; k < 64; k++) {
        float qr[4], kr[4];
        #pragma unroll
        for (int i = 0; i < 4; i++) qr[i] = Qs[k][tm + i];
        #pragma unroll
        for (int j = 0; j < 4; j++) kr[j] = Ks[k][tn + j];
        #pragma unroll
        for (int i = 0; i < 4; i++)
            #pragma unroll
            for (int j = 0; j < 4; j++) acc[i][j] += qr[i] * kr[j];
    }

    const float scale = 0.125f;   // 1/sqrt(64)
    size_t base = (size_t)bh * T_ * S_;
    #pragma unroll
    for (int i = 0; i < 4; i++)
        #pragma unroll
        for (int j = 0; j < 4; j++)
            P[base + (size_t)(t0 + tm + i) * S_ + s0 + tn + j] = acc[i][j] * scale;
}

// ---------------------------------------------------------------------------
// Kernel 4: row softmax over S=2048, one block (256 thr) per row, in-place.
// ---------------------------------------------------------------------------
__global__ __launch_bounds__(256)
void softmax_kernel(float* __restrict__ P) {
    size_t row = blockIdx.x;
    float* p = P + row * (size_t)S_;
    int tid = threadIdx.x;
    float v[8];
    float mx = -1e30f;
    #pragma unroll
    for (int i = 0; i < 8; i++) {
        v[i] = p[tid + i * 256];
        mx = fmaxf(mx, v[i]);
    }
    __shared__ float red[8];
    #pragma unroll
    for (int o = 16; o; o >>= 1) mx = fmaxf(mx, __shfl_xor_sync(~0u, mx, o));
    if ((tid & 31) == 0) red[tid >> 5] = mx;
    __syncthreads();
    mx = red[0];
    #pragma unroll
    for (int i = 1; i < 8; i++) mx = fmaxf(mx, red[i]);
    __syncthreads();

    float sum = 0.f;
    #pragma unroll
    for (int i = 0; i < 8; i++) {
        v[i] = __expf(v[i] - mx);
        sum += v[i];
    }
    #pragma unroll
    for (int o = 16; o; o >>= 1) sum += __shfl_xor_sync(~0u, sum, o);
    if ((tid & 31) == 0) red[tid >> 5] = sum;
    __syncthreads();
    sum = 0.f;
    #pragma unroll
    for (int i = 0; i < 8; i++) sum += red[i];
    float inv = 1.0f / sum;
    #pragma unroll
    for (int i = 0; i < 8; i++) p[tid + i * 256] = v[i] * inv;
}

// ---------------------------------------------------------------------------
// Kernel 5: attn_w[b,t,s] = mean over h of P[(b*16+h), t, s]
// ---------------------------------------------------------------------------
__global__ void attnw_kernel(const float* __restrict__ P, float* __restrict__ Wout) {
    size_t idx = (size_t)blockIdx.x * blockDim.x + threadIdx.x;
    if (idx >= OUT2_ELEMS) return;
    size_t b  = idx / ((size_t)T_ * S_);
    size_t ts = idx % ((size_t)T_ * S_);
    float s = 0.f;
    #pragma unroll
    for (int h = 0; h < H_; h++)
        s += P[((b * H_ + h) * (size_t)T_ * S_) + ts];
    Wout[idx] = s * (1.0f / H_);
}

// ---------------------------------------------------------------------------
// Kernel 6: PV  O[(t*B+b)*E + h*64+d] = sum_s P[bh,t,s] * V[(s*B+b)*E + h*64+d]
// 64(t) x 64(d) tile, BK=32 over S, 256 threads, 4x4 per thread.
// ---------------------------------------------------------------------------
__global__ __launch_bounds__(256)
void pv_kernel(const float* __restrict__ P, const float* __restrict__ V,
               float* __restrict__ O) {
    int bh = blockIdx.z;
    int b = bh >> 4, h = bh & 15;
    int t0 = blockIdx.x * 64;

    __shared__ float Ps[32][65];   // [k][t]
    __shared__ float Vs[32][64];   // [k][d]

    int tid = threadIdx.x;
    int tm = (tid >> 4) * 4;
    int tn = (tid & 15) * 4;
    float acc[4][4];
    #pragma unroll
    for (int i = 0; i < 4; i++)
        #pragma unroll
        for (int j = 0; j < 4; j++) acc[i][j] = 0.f;

    size_t pbase = ((size_t)bh * T_ + t0) * S_;

    for (int k0 = 0; k0 < S_; k0 += 32) {
        // load P tile: 64 t-rows x 32 s-cols (2 float4 / thread), transposed
        #pragma unroll
        for (int i = 0; i < 2; i++) {
            int trow = (tid >> 3) + i * 32;
            int scol = (tid & 7) * 4;
            float4 pv = *(const float4*)(P + pbase + (size_t)trow * S_ + k0 + scol);
            Ps[scol + 0][trow] = pv.x; Ps[scol + 1][trow] = pv.y;
            Ps[scol + 2][trow] = pv.z; Ps[scol + 3][trow] = pv.w;
        }
        // load V tile: 32 s-rows x 64 d-cols (2 float4 / thread)
        #pragma unroll
        for (int i = 0; i < 2; i++) {
            int vrow = (tid >> 4) + i * 16;
            int dcol = (tid & 15) * 4;
            size_t va = ((size_t)(k0 + vrow) * B_ + b) * E_ + h * HD_ + dcol;
            *(float4*)&Vs[vrow][dcol] = *(const float4*)(V + va);
        }
        __syncthreads();
        #pragma unroll
        for (int k = 0; k < 32; k++) {
            float pr[4], vr[4];
            #pragma unroll
            for (int i = 0; i < 4; i++) pr[i] = Ps[k][tm + i];
            #pragma unroll
            for (int j = 0; j < 4; j++) vr[j] = Vs[k][tn + j];
            #pragma unroll
            for (int i = 0; i < 4; i++)
                #pragma unroll
                for (int j = 0; j < 4; j++) acc[i][j] += pr[i] * vr[j];
        }
        __syncthreads();
    }

    #pragma unroll
    for (int i = 0; i < 4; i++) {
        size_t obase = ((size_t)(t0 + tm + i) * B_ + b) * E_ + h * HD_;
        #pragma unroll
        for (int j = 0; j < 4; j++)
            O[obase + tn + j] = acc[i][j];
    }
}

// ---------------------------------------------------------------------------
// Host launcher
// ---------------------------------------------------------------------------
extern "C" void kernel_launch(void* const* d_in, const int* in_sizes, int n_in,
                              void* d_out, int out_size) {
    const float* query = (const float*)d_in[0];
    const float* key   = (const float*)d_in[1];
    const float* value = (const float*)d_in[2];
    const float* q_w  = (const float*)d_in[3];
    const float* q_b  = (const float*)d_in[4];
    const float* q_la = (const float*)d_in[5];
    const float* q_lb = (const float*)d_in[6];
    const float* k_w  = (const float*)d_in[7];
    const float* k_b  = (const float*)d_in[8];
    const float* k_la = (const float*)d_in[9];
    const float* k_lb = (const float*)d_in[10];
    const float* v_w  = (const float*)d_in[11];
    const float* v_b  = (const float*)d_in[12];
    const float* v_la = (const float*)d_in[13];
    const float* v_lb = (const float*)d_in[14];
    const float* o_w  = (const float*)d_in[15];
    const float* o_b  = (const float*)d_in[16];
    const float* o_la = (const float*)d_in[17];
    const float* o_lb = (const float*)d_in[18];

    float *Q, *K, *V, *O, *P, *Xa;
    cudaGetSymbolAddress((void**)&Q,  g_Q);
    cudaGetSymbolAddress((void**)&K,  g_K);
    cudaGetSymbolAddress((void**)&V,  g_V);
    cudaGetSymbolAddress((void**)&O,  g_O);
    cudaGetSymbolAddress((void**)&P,  g_P);
    cudaGetSymbolAddress((void**)&Xa, g_Xa);
    float* XaQ = Xa;
    float* XaK = Xa + (size_t)M_ * R_;
    float* XaV = Xa + 2 * (size_t)M_ * R_;
    float* XaO = Xa + 3 * (size_t)M_ * R_;

    float* out1 = (float*)d_out;
    bool write_attnw = ((size_t)out_size >= OUT1_ELEMS + OUT2_ELEMS);
    float* out2 = out1 + OUT1_ELEMS;

    dim3 gGemm(E_ / 128, M_ / 128);      // (8, 32)

    // LoRA-A for q,k,v
    lora_a_kernel<<<M_, 128>>>(query, q_la, XaQ);
    lora_a_kernel<<<M_, 128>>>(key,   k_la, XaK);
    lora_a_kernel<<<M_, 128>>>(value, v_la, XaV);

    // projections
    gemm_lora_kernel<<<gGemm, 256>>>(query, q_w, q_b, XaQ, q_lb, Q);
    gemm_lora_kernel<<<gGemm, 256>>>(key,   k_w, k_b, XaK, k_lb, K);
    gemm_lora_kernel<<<gGemm, 256>>>(value, v_w, v_b, XaV, v_lb, V);

    // scores
    dim3 gScores(S_ / 64, T_ / 64, BH_);  // (32, 32, 32)
    scores_kernel<<<gScores, 256>>>(Q, K, P);

    // softmax (in place)
    softmax_kernel<<<BH_ * T_, 256>>>(P);

    // attn_w mean over heads
    if (write_attnw) {
        int nblk = (int)((OUT2_ELEMS + 255) / 256);
        attnw_kernel<<<nblk, 256>>>(P, out2);
    }

    // P @ V
    dim3 gPV(T_ / 64, 1, BH_);            // (32, 1, 32)
    pv_kernel<<<gPV, 256>>>(P, V, O);

    // output projection
    lora_a_kernel<<<M_, 128>>>(O, o_la, XaO);
    gemm_lora_kernel<<<gGemm, 256>>>(O, o_w, o_b, XaO, o_lb, out1);
}

// round 6
// speedup vs baseline: 1.2399x; 1.2399x over previous
#include <cuda_runtime.h>
#include <cuda_bf16.h>
#include <cstdint>
#include <math.h>

// Problem constants
#define T_  2048
#define B_  2
#define S_  2048
#define E_  1024
#define H_  16
#define HD_ 64
#define R_  16
#define M_  (T_ * B_)          // 4096 rows for projections
#define BH_ (B_ * H_)          // 32 attention "batches"
#define SCALING 1.0f           // ALPHA / R = 16/16
#define OUT1_ELEMS ((size_t)T_ * B_ * E_)            // 4,194,304
#define OUT2_ELEMS ((size_t)B_ * T_ * S_)            // 8,388,608

// ---------------------------------------------------------------------------
// Static device scratch (no allocations allowed)
// ---------------------------------------------------------------------------
__device__ float g_Q[M_ * E_];
__device__ float g_K[M_ * E_];
__device__ float g_V[M_ * E_];
__device__ float g_O[M_ * E_];
__device__ float g_P[(size_t)BH_ * T_ * S_];          // 512 MB scores/probs
__device__ float g_Xa[4 * M_ * R_];                   // LoRA-A activations

// ---------------------------------------------------------------------------
// mma.sync helpers (portable sm_80+ path; tcgen05 is NOT available: the
// harness ptxas targets plain sm_103, which rejects arch-specific features)
// ---------------------------------------------------------------------------
__device__ __forceinline__ uint32_t smem_u32(const void* p) {
    uint32_t a;
    asm("{ .reg .u64 t; cvta.to.shared.u64 t, %1; cvt.u32.u64 %0, t; }" : "=r"(a) : "l"(p));
    return a;
}
#define LDMATRIX_X4(r, addr) \
    asm volatile("ldmatrix.sync.aligned.m8n8.x4.shared.b16 {%0,%1,%2,%3}, [%4];" \
        : "=r"((r)[0]), "=r"((r)[1]), "=r"((r)[2]), "=r"((r)[3]) : "r"(addr))
#define MMA_BF16(d, a, b) \
    asm volatile("mma.sync.aligned.m16n8k16.row.col.f32.bf16.bf16.f32 " \
        "{%0,%1,%2,%3}, {%4,%5,%6,%7}, {%8,%9}, {%0,%1,%2,%3};" \
        : "+f"((d)[0]), "+f"((d)[1]), "+f"((d)[2]), "+f"((d)[3]) \
        : "r"((a)[0]), "r"((a)[1]), "r"((a)[2]), "r"((a)[3]), \
          "r"((b)[0]), "r"((b)[1]))

// ---------------------------------------------------------------------------
// Kernel 1: LoRA-A  Xa[m,r] = sum_e X[m,e] * la[r,e]
// ---------------------------------------------------------------------------
__global__ void lora_a_kernel(const float* __restrict__ X,
                              const float* __restrict__ la,
                              float* __restrict__ Xa) {
    int m = blockIdx.x;
    int t = threadIdx.x;          // 128
    int r  = t & 15;
    int eo = t >> 4;              // 0..7
    const float* x   = X  + (size_t)m * E_;
    const float* lar = la + (size_t)r * E_;
    float acc = 0.f;
    #pragma unroll 8
    for (int e = eo; e < E_; e += 8) acc += x[e] * lar[e];
    __shared__ float sm[16][8];
    sm[r][eo] = acc;
    __syncthreads();
    if (t < 16) {
        float s = 0.f;
        #pragma unroll
        for (int i = 0; i < 8; i++) s += sm[t][i];
        Xa[(size_t)m * R_ + t] = s;
    }
}

// ---------------------------------------------------------------------------
// Kernel 2: bf16 mma.sync (3-term hi/lo split) GEMM + LoRA + bias
// C[m,n] = sum_k A[m,k]*W[n,k] + bias[n] + SCALING*sum_r Xa[m,r]*lb[n,r]
// Block tile 128x128, 8 warps (2x4) of 64x32 warp tiles, BK=64 fp32 chunks,
// LoRA folded as zero-padded chunk 16.  Double-buffered smem + LDG prefetch.
// ---------------------------------------------------------------------------
#define GNC     17               // 16 K-chunks + 1 LoRA chunk
#define SKS     72               // smem row stride (bf16 elems): 144B, conflict-free
#define MAT_B   (128 * SKS * 2)  // one bf16 matrix buffer: 18432 B
#define SMEM_GEMM_TOTAL (8 * MAT_B + 512)

__device__ __forceinline__ void ldg_chunk(
    const float* __restrict__ A, const float* __restrict__ W,
    const float* __restrict__ Xa, const float* __restrict__ lb,
    int chunk, int m0, int n0, int tid, float* rA, float* rW)
{
    int r  = tid >> 1;            // 0..127
    int c0 = (tid & 1) * 32;      // 0 or 32
    if (chunk < 16) {
        const float* pa = A + (size_t)(m0 + r) * E_ + chunk * 64 + c0;
        const float* pw = W + (size_t)(n0 + r) * E_ + chunk * 64 + c0;
        #pragma unroll
        for (int i = 0; i < 8; i++) {
            float4 v = *(const float4*)(pa + i * 4);
            rA[4*i+0] = v.x; rA[4*i+1] = v.y; rA[4*i+2] = v.z; rA[4*i+3] = v.w;
            float4 w = *(const float4*)(pw + i * 4);
            rW[4*i+0] = w.x; rW[4*i+1] = w.y; rW[4*i+2] = w.z; rW[4*i+3] = w.w;
        }
    } else {
        #pragma unroll
        for (int i = 0; i < 32; i++) { rA[i] = 0.f; rW[i] = 0.f; }
        if (c0 == 0) {
            const float* px = Xa + (size_t)(m0 + r) * R_;
            const float* pl = lb + (size_t)(n0 + r) * R_;
            #pragma unroll
            for (int i = 0; i < 4; i++) {
                float4 v = *(const float4*)(px + i * 4);
                rA[4*i+0] = SCALING * v.x; rA[4*i+1] = SCALING * v.y;
                rA[4*i+2] = SCALING * v.z; rA[4*i+3] = SCALING * v.w;
                float4 w = *(const float4*)(pl + i * 4);
                rW[4*i+0] = w.x; rW[4*i+1] = w.y; rW[4*i+2] = w.z; rW[4*i+3] = w.w;
            }
        }
    }
}

__device__ __forceinline__ void split_pair(float f0, float f1,
                                           __nv_bfloat162* hi, __nv_bfloat162* lo) {
    __nv_bfloat16 h0 = __float2bfloat16_rn(f0);
    __nv_bfloat16 h1 = __float2bfloat16_rn(f1);
    __nv_bfloat16 l0 = __float2bfloat16_rn(f0 - __bfloat162float(h0));
    __nv_bfloat16 l1 = __float2bfloat16_rn(f1 - __bfloat162float(h1));
    *hi = __nv_bfloat162(h0, h1);
    *lo = __nv_bfloat162(l0, l1);
}

__device__ __forceinline__ void sts_chunk(
    char* sm, int buf, int tid, const float* rA, const float* rW)
{
    int r  = tid >> 1;
    int c0 = (tid & 1) * 32;
    __nv_bfloat16* Ahi = (__nv_bfloat16*)(sm + (buf * 4 + 0) * MAT_B);
    __nv_bfloat16* Alo = (__nv_bfloat16*)(sm + (buf * 4 + 1) * MAT_B);
    __nv_bfloat16* Whi = (__nv_bfloat16*)(sm + (buf * 4 + 2) * MAT_B);
    __nv_bfloat16* Wlo = (__nv_bfloat16*)(sm + (buf * 4 + 3) * MAT_B);
    #pragma unroll
    for (int p = 0; p < 16; p++) {
        int off = r * SKS + c0 + 2 * p;
        __nv_bfloat162 h, l;
        split_pair(rA[2*p], rA[2*p+1], &h, &l);
        *(__nv_bfloat162*)&Ahi[off] = h;
        *(__nv_bfloat162*)&Alo[off] = l;
        split_pair(rW[2*p], rW[2*p+1], &h, &l);
        *(__nv_bfloat162*)&Whi[off] = h;
        *(__nv_bfloat162*)&Wlo[off] = l;
    }
}

__global__ __launch_bounds__(256, 1)
void gemm_lora_mma(const float* __restrict__ A, const float* __restrict__ W,
                   const float* __restrict__ bias, const float* __restrict__ Xa,
                   const float* __restrict__ lb, float* __restrict__ C)
{
    extern __shared__ char sm[];
    float* biasS = (float*)(sm + 8 * MAT_B);

    int tid = threadIdx.x;
    int wid = tid >> 5;
    int lane = tid & 31;
    int warp_m = wid >> 2;       // 0..1
    int warp_n = wid & 3;        // 0..3
    int m0 = blockIdx.y * 128;
    int n0 = blockIdx.x * 128;

    if (tid < 128) biasS[tid] = bias[n0 + tid];

    float acc[4][4][4];
    #pragma unroll
    for (int i = 0; i < 4; i++)
        #pragma unroll
        for (int j = 0; j < 4; j++)
            #pragma unroll
            for (int q = 0; q < 4; q++) acc[i][j][q] = 0.f;

    float rA[32], rW[32];
    ldg_chunk(A, W, Xa, lb, 0, m0, n0, tid, rA, rW);
    sts_chunk(sm, 0, tid, rA, rW);
    __syncthreads();

    // ldmatrix base offsets (constant per thread)
    int a_row = warp_m * 64 + (lane & 15);
    int a_colk = (lane >> 4) * 8;                        // 0 or 8 within k16
    int b_row = warp_n * 32 + ((lane >> 4) << 3) + (lane & 7);
    int b_colk = ((lane >> 3) & 1) * 8;

    for (int c = 0; c < GNC; c++) {
        if (c + 1 < GNC) ldg_chunk(A, W, Xa, lb, c + 1, m0, n0, tid, rA, rW);

        int buf = c & 1;
        uint32_t sAhi = smem_u32(sm + (buf * 4 + 0) * MAT_B);
        uint32_t sAlo = smem_u32(sm + (buf * 4 + 1) * MAT_B);
        uint32_t sWhi = smem_u32(sm + (buf * 4 + 2) * MAT_B);
        uint32_t sWlo = smem_u32(sm + (buf * 4 + 3) * MAT_B);

        #pragma unroll
        for (int kk = 0; kk < 4; kk++) {
            int k0 = kk * 16;
            uint32_t ahi[4][4], alo[4][4];
            #pragma unroll
            for (int i = 0; i < 4; i++) {
                uint32_t off = (uint32_t)(((a_row + i * 16) * SKS) + k0 + a_colk) * 2;
                LDMATRIX_X4(ahi[i], sAhi + off);
                LDMATRIX_X4(alo[i], sAlo + off);
            }
            uint32_t bhi[4][2], blo[4][2];
            #pragma unroll
            for (int jp = 0; jp < 2; jp++) {
                uint32_t off = (uint32_t)(((b_row + jp * 16) * SKS) + k0 + b_colk) * 2;
                uint32_t t[4];
                LDMATRIX_X4(t, sWhi + off);
                bhi[jp*2][0] = t[0]; bhi[jp*2][1] = t[1];
                bhi[jp*2+1][0] = t[2]; bhi[jp*2+1][1] = t[3];
                LDMATRIX_X4(t, sWlo + off);
                blo[jp*2][0] = t[0]; blo[jp*2][1] = t[1];
                blo[jp*2+1][0] = t[2]; blo[jp*2+1][1] = t[3];
            }
            #pragma unroll
            for (int i = 0; i < 4; i++)
                #pragma unroll
                for (int j = 0; j < 4; j++) {
                    MMA_BF16(acc[i][j], ahi[i], bhi[j]);
                    MMA_BF16(acc[i][j], ahi[i], blo[j]);
                    MMA_BF16(acc[i][j], alo[i], bhi[j]);
                }
        }
        __syncthreads();
        if (c + 1 < GNC) {
            sts_chunk(sm, (c + 1) & 1, tid, rA, rW);
            __syncthreads();
        }
    }

    // epilogue: add bias, store fp32
    int g  = lane >> 2;
    int tg = lane & 3;
    #pragma unroll
    for (int i = 0; i < 4; i++) {
        int row = m0 + warp_m * 64 + i * 16 + g;
        #pragma unroll
        for (int j = 0; j < 4; j++) {
            int colb = warp_n * 32 + j * 8 + 2 * tg;
            float b0 = biasS[colb], b1 = biasS[colb + 1];
            float2 v0 = make_float2(acc[i][j][0] + b0, acc[i][j][1] + b1);
            float2 v1 = make_float2(acc[i][j][2] + b0, acc[i][j][3] + b1);
            *(float2*)&C[(size_t)row * E_ + n0 + colb] = v0;
            *(float2*)&C[(size_t)(row + 8) * E_ + n0 + colb] = v1;
        }
    }
}

// ---------------------------------------------------------------------------
// Kernel 3: scores  P[bh, t, s] = (1/8) * sum_d Q[t,b,h*64+d] * K[s,b,h*64+d]
// ---------------------------------------------------------------------------
__global__ __launch_bounds__(256)
void scores_kernel(const float* __restrict__ Q, const float* __restrict__ Kp,
                   float* __restrict__ P) {
    int bh = blockIdx.z;
    int b = bh >> 4, h = bh & 15;
    int t0 = blockIdx.y * 64;
    int s0 = blockIdx.x * 64;

    __shared__ float Qs[64][65];   // [d][t]
    __shared__ float Ks[64][65];   // [d][s]

    int tid = threadIdx.x;
    #pragma unroll
    for (int i = 0; i < 4; i++) {
        int row  = (tid >> 4) + i * 16;
        int dcol = (tid & 15) * 4;
        size_t qa = ((size_t)(t0 + row) * B_ + b) * E_ + h * HD_ + dcol;
        size_t ka = ((size_t)(s0 + row) * B_ + b) * E_ + h * HD_ + dcol;
        float4 qv = *(const float4*)(Q + qa);
        float4 kv = *(const float4*)(Kp + ka);
        Qs[dcol + 0][row] = qv.x; Qs[dcol + 1][row] = qv.y;
        Qs[dcol + 2][row] = qv.z; Qs[dcol + 3][row] = qv.w;
        Ks[dcol + 0][row] = kv.x; Ks[dcol + 1][row] = kv.y;
        Ks[dcol + 2][row] = kv.z; Ks[dcol + 3][row] = kv.w;
    }
    __syncthreads();

    int tm = (tid >> 4) * 4;
    int tn = (tid & 15) * 4;
    float acc[4][4];
    #pragma unroll
    for (int i = 0; i < 4; i++)
        #pragma unroll
        for (int j = 0; j < 4; j++) acc[i][j] = 0.f;

    #pragma unroll 8
    for (int k = 0; k < 64; k++) {
        float qr[4], kr[4];
        #pragma unroll
        for (int i = 0; i < 4; i++) qr[i] = Qs[k][tm + i];
        #pragma unroll
        for (int j = 0; j < 4; j++) kr[j] = Ks[k][tn + j];
        #pragma unroll
        for (int i = 0; i < 4; i++)
            #pragma unroll
            for (int j = 0; j < 4; j++) acc[i][j] += qr[i] * kr[j];
    }

    const float scale = 0.125f;
    size_t base = (size_t)bh * T_ * S_;
    #pragma unroll
    for (int i = 0; i < 4; i++)
        #pragma unroll
        for (int j = 0; j < 4; j++)
            P[base + (size_t)(t0 + tm + i) * S_ + s0 + tn + j] = acc[i][j] * scale;
}

// ---------------------------------------------------------------------------
// Kernel 4: row softmax over S=2048
// ---------------------------------------------------------------------------
__global__ __launch_bounds__(256)
void softmax_kernel(float* __restrict__ P) {
    size_t row = blockIdx.x;
    float* p = P + row * (size_t)S_;
    int tid = threadIdx.x;
    float v[8];
    float mx = -1e30f;
    #pragma unroll
    for (int i = 0; i < 8; i++) {
        v[i] = p[tid + i * 256];
        mx = fmaxf(mx, v[i]);
    }
    __shared__ float red[8];
    #pragma unroll
    for (int o = 16; o; o >>= 1) mx = fmaxf(mx, __shfl_xor_sync(~0u, mx, o));
    if ((tid & 31) == 0) red[tid >> 5] = mx;
    __syncthreads();
    mx = red[0];
    #pragma unroll
    for (int i = 1; i < 8; i++) mx = fmaxf(mx, red[i]);
    __syncthreads();

    float sum = 0.f;
    #pragma unroll
    for (int i = 0; i < 8; i++) {
        v[i] = __expf(v[i] - mx);
        sum += v[i];
    }
    #pragma unroll
    for (int o = 16; o; o >>= 1) sum += __shfl_xor_sync(~0u, sum, o);
    if ((tid & 31) == 0) red[tid >> 5] = sum;
    __syncthreads();
    sum = 0.f;
    #pragma unroll
    for (int i = 0; i < 8; i++) sum += red[i];
    float inv = 1.0f / sum;
    #pragma unroll
    for (int i = 0; i < 8; i++) p[tid + i * 256] = v[i] * inv;
}

// ---------------------------------------------------------------------------
// Kernel 5: attn_w[b,t,s] = mean over h of P[(b*16+h), t, s]
// ---------------------------------------------------------------------------
__global__ void attnw_kernel(const float* __restrict__ P, float* __restrict__ Wout) {
    size_t idx = (size_t)blockIdx.x * blockDim.x + threadIdx.x;
    if (idx >= OUT2_ELEMS) return;
    size_t b  = idx / ((size_t)T_ * S_);
    size_t ts = idx % ((size_t)T_ * S_);
    float s = 0.f;
    #pragma unroll
    for (int h = 0; h < H_; h++)
        s += P[((b * H_ + h) * (size_t)T_ * S_) + ts];
    Wout[idx] = s * (1.0f / H_);
}

// ---------------------------------------------------------------------------
// Kernel 6: PV
// ---------------------------------------------------------------------------
__global__ __launch_bounds__(256)
void pv_kernel(const float* __restrict__ P, const float* __restrict__ V,
               float* __restrict__ O) {
    int bh = blockIdx.z;
    int b = bh >> 4, h = bh & 15;
    int t0 = blockIdx.x * 64;

    __shared__ float Ps[32][65];
    __shared__ float Vs[32][64];

    int tid = threadIdx.x;
    int tm = (tid >> 4) * 4;
    int tn = (tid & 15) * 4;
    float acc[4][4];
    #pragma unroll
    for (int i = 0; i < 4; i++)
        #pragma unroll
        for (int j = 0; j < 4; j++) acc[i][j] = 0.f;

    size_t pbase = ((size_t)bh * T_ + t0) * S_;

    for (int k0 = 0; k0 < S_; k0 += 32) {
        #pragma unroll
        for (int i = 0; i < 2; i++) {
            int trow = (tid >> 3) + i * 32;
            int scol = (tid & 7) * 4;
            float4 pv = *(const float4*)(P + pbase + (size_t)trow * S_ + k0 + scol);
            Ps[scol + 0][trow] = pv.x; Ps[scol + 1][trow] = pv.y;
            Ps[scol + 2][trow] = pv.z; Ps[scol + 3][trow] = pv.w;
        }
        #pragma unroll
        for (int i = 0; i < 2; i++) {
            int vrow = (tid >> 4) + i * 16;
            int dcol = (tid & 15) * 4;
            size_t va = ((size_t)(k0 + vrow) * B_ + b) * E_ + h * HD_ + dcol;
            *(float4*)&Vs[vrow][dcol] = *(const float4*)(V + va);
        }
        __syncthreads();
        #pragma unroll
        for (int k = 0; k < 32; k++) {
            float pr[4], vr[4];
            #pragma unroll
            for (int i = 0; i < 4; i++) pr[i] = Ps[k][tm + i];
            #pragma unroll
            for (int j = 0; j < 4; j++) vr[j] = Vs[k][tn + j];
            #pragma unroll
            for (int i = 0; i < 4; i++)
                #pragma unroll
                for (int j = 0; j < 4; j++) acc[i][j] += pr[i] * vr[j];
        }
        __syncthreads();
    }

    #pragma unroll
    for (int i = 0; i < 4; i++) {
        size_t obase = ((size_t)(t0 + tm + i) * B_ + b) * E_ + h * HD_;
        #pragma unroll
        for (int j = 0; j < 4; j++)
            O[obase + tn + j] = acc[i][j];
    }
}

// ---------------------------------------------------------------------------
// Host launcher
// ---------------------------------------------------------------------------
extern "C" void kernel_launch(void* const* d_in, const int* in_sizes, int n_in,
                              void* d_out, int out_size) {
    const float* query = (const float*)d_in[0];
    const float* key   = (const float*)d_in[1];
    const float* value = (const float*)d_in[2];
    const float* q_w  = (const float*)d_in[3];
    const float* q_b  = (const float*)d_in[4];
    const float* q_la = (const float*)d_in[5];
    const float* q_lb = (const float*)d_in[6];
    const float* k_w  = (const float*)d_in[7];
    const float* k_b  = (const float*)d_in[8];
    const float* k_la = (const float*)d_in[9];
    const float* k_lb = (const float*)d_in[10];
    const float* v_w  = (const float*)d_in[11];
    const float* v_b  = (const float*)d_in[12];
    const float* v_la = (const float*)d_in[13];
    const float* v_lb = (const float*)d_in[14];
    const float* o_w  = (const float*)d_in[15];
    const float* o_b  = (const float*)d_in[16];
    const float* o_la = (const float*)d_in[17];
    const float* o_lb = (const float*)d_in[18];

    float *Q, *K, *V, *O, *P, *Xa;
    cudaGetSymbolAddress((void**)&Q,  g_Q);
    cudaGetSymbolAddress((void**)&K,  g_K);
    cudaGetSymbolAddress((void**)&V,  g_V);
    cudaGetSymbolAddress((void**)&O,  g_O);
    cudaGetSymbolAddress((void**)&P,  g_P);
    cudaGetSymbolAddress((void**)&Xa, g_Xa);
    float* XaQ = Xa;
    float* XaK = Xa + (size_t)M_ * R_;
    float* XaV = Xa + 2 * (size_t)M_ * R_;
    float* XaO = Xa + 3 * (size_t)M_ * R_;

    float* out1 = (float*)d_out;
    bool write_attnw = ((size_t)out_size >= OUT1_ELEMS + OUT2_ELEMS);
    float* out2 = out1 + OUT1_ELEMS;

    cudaFuncSetAttribute(gemm_lora_mma, cudaFuncAttributeMaxDynamicSharedMemorySize,
                         SMEM_GEMM_TOTAL);

    dim3 gGemm(E_ / 128, M_ / 128);      // (8, 32)

    // LoRA-A for q,k,v
    lora_a_kernel<<<M_, 128>>>(query, q_la, XaQ);
    lora_a_kernel<<<M_, 128>>>(key,   k_la, XaK);
    lora_a_kernel<<<M_, 128>>>(value, v_la, XaV);

    // projections via bf16 mma.sync (3-term split)
    gemm_lora_mma<<<gGemm, 256, SMEM_GEMM_TOTAL>>>(query, q_w, q_b, XaQ, q_lb, Q);
    gemm_lora_mma<<<gGemm, 256, SMEM_GEMM_TOTAL>>>(key,   k_w, k_b, XaK, k_lb, K);
    gemm_lora_mma<<<gGemm, 256, SMEM_GEMM_TOTAL>>>(value, v_w, v_b, XaV, v_lb, V);

    // scores
    dim3 gScores(S_ / 64, T_ / 64, BH_);
    scores_kernel<<<gScores, 256>>>(Q, K, P);

    // softmax (in place)
    softmax_kernel<<<BH_ * T_, 256>>>(P);

    // attn_w mean over heads
    if (write_attnw) {
        int nblk = (int)((OUT2_ELEMS + 255) / 256);
        attnw_kernel<<<nblk, 256>>>(P, out2);
    }

    // P @ V
    dim3 gPV(T_ / 64, 1, BH_);
    pv_kernel<<<gPV, 256>>>(P, V, O);

    // output projection
    lora_a_kernel<<<M_, 128>>>(O, o_la, XaO);
    gemm_lora_mma<<<gGemm, 256, SMEM_GEMM_TOTAL>>>(O, o_w, o_b, XaO, o_lb, out1);
}